// round 3
// baseline (speedup 1.0000x reference)
#include <cuda_runtime.h>
#include <mma.h>
#include <math.h>
#include <stdint.h>

using namespace nvcuda;

#define BNUM  50
#define E0    600000
#define FIN   256
#define NH    128
#define N0MAX 100000
#define N1MAX 80000

// ---------------- scratch (device globals; no allocs allowed) ----------------
__device__ float g_h[N0MAX * NH];        // GEMM output h = x @ W
__device__ float g_xa[N0MAX * NH];       // conv output x' (post-relu)
__device__ float g_xb[N1MAX * NH];       // pooled features
__device__ float g_hs[N0MAX];            // score projection h_s = x' @ Ws
__device__ float g_score[N0MAX];
__device__ int   g_deg[N0MAX];
__device__ float g_dis[N0MAX];           // rsqrt(deg+1)
__device__ float g_dinv[N0MAX];          // 1/(deg+1)
__device__ int   g_rowptr[N0MAX + 1];
__device__ int   g_cursor[N0MAX];
__device__ int   g_exsc[N0MAX];
__device__ int   g_bsum[128];
__device__ int   g_csr[E0];              // src ids bucketed by dst
__device__ int   g_esrc0[E0], g_edst0[E0];
__device__ int   g_esrc1[E0], g_edst1[E0];
__device__ int   g_perm[N1MAX];
__device__ int   g_map[N0MAX];
__device__ float g_x123[BNUM * 2 * NH];  // x1+x2+x3 accumulator
__device__ int   g_cnt[4];
// transposed tf32-split weights: B[n][k] = W[k][n].  s1 @0 (128x256), s2 @32768, s3 @49152
__device__ float g_Wh[65536], g_Wl[65536];

__device__ __forceinline__ uint32_t tf32_rna(float x) {
    uint32_t r; asm("cvt.rna.tf32.f32 %0, %1;" : "=r"(r) : "f"(x)); return r;
}

// ---------------- small kernels ----------------
__global__ void k_init() {
    int t = blockIdx.x * blockDim.x + threadIdx.x;
    if (t < BNUM * 2 * NH) g_x123[t] = 0.f;
    if (t == 0) { g_cnt[0] = E0; g_cnt[1] = 0; g_cnt[2] = 0; }
}

__global__ void k_splitW(const float* __restrict__ W1, const float* __restrict__ W2,
                         const float* __restrict__ W3) {
    int t = blockIdx.x * blockDim.x + threadIdx.x;
    if (t >= 65536) return;
    float x;
    if (t < 32768)      { int n = t >> 8, k = t & 255; x = W1[k * 128 + n]; }
    else if (t < 49152) { int u = t - 32768; int n = u >> 7, k = u & 127; x = W2[k * 128 + n]; }
    else                { int u = t - 49152; int n = u >> 7, k = u & 127; x = W3[k * 128 + n]; }
    uint32_t h = tf32_rna(x);
    float lo = x - __uint_as_float(h);
    g_Wh[t] = __uint_as_float(h);
    g_Wl[t] = __uint_as_float(tf32_rna(lo));
}

__global__ void k_reset(int N) {
    int i = blockIdx.x * blockDim.x + threadIdx.x;
    if (i < N) { g_deg[i] = 0; g_map[i] = -1; }
}

__global__ void k_count(const int* __restrict__ dst, const int* __restrict__ cnt) {
    int i = blockIdx.x * blockDim.x + threadIdx.x;
    if (i < *cnt) atomicAdd(&g_deg[dst[i]], 1);
}

// scan part 1 + fused degnorm
__global__ void k_scan1(int N) {
    __shared__ int sm[1024];
    int i = blockIdx.x * 1024 + threadIdx.x;
    int v = (i < N) ? g_deg[i] : 0;
    if (i < N) {
        float d = (float)v + 1.0f;
        g_dinv[i] = 1.0f / d;
        g_dis[i]  = rsqrtf(d);
    }
    sm[threadIdx.x] = v;
    __syncthreads();
    for (int off = 1; off < 1024; off <<= 1) {
        int t = (threadIdx.x >= off) ? sm[threadIdx.x - off] : 0;
        __syncthreads();
        sm[threadIdx.x] += t;
        __syncthreads();
    }
    if (i < N) g_exsc[i] = sm[threadIdx.x] - v;
    if (threadIdx.x == 1023) g_bsum[blockIdx.x] = sm[1023];
}

__global__ void k_scan2(int nb) {
    if (threadIdx.x == 0) {
        int run = 0;
        for (int i = 0; i < nb; i++) { int t = g_bsum[i]; g_bsum[i] = run; run += t; }
    }
}

__global__ void k_scan3(int N, const int* __restrict__ cnt) {
    int i = blockIdx.x * blockDim.x + threadIdx.x;
    if (i < N) {
        int r = g_exsc[i] + g_bsum[i >> 10];
        g_rowptr[i] = r;
        g_cursor[i] = r;
    }
    if (i == 0) g_rowptr[N] = *cnt;
}

__global__ void k_csr(const int* __restrict__ src, const int* __restrict__ dst,
                      const int* __restrict__ cnt) {
    int i = blockIdx.x * blockDim.x + threadIdx.x;
    if (i < *cnt) {
        int d = dst[i];
        int p = atomicAdd(&g_cursor[d], 1);
        g_csr[p] = src[i];
    }
}

// ---------------- wmma tf32 3x-split GEMM: H[N,128] = X[N,F] @ W[F,128] -------------
// Bh/Bl hold W^T split hi/lo: [128 rows(n) x F] row-major (= col-major k x n).
// BM=128, BN=128, BK=32, 256 threads; 8 warps each own 64x32 (4x2 m16n16k8 tiles).
#define LDS_A 36
__global__ __launch_bounds__(256)
void k_gemm_mma(const float* __restrict__ X, const float* __restrict__ Bhg,
                const float* __restrict__ Blg, int N, int F, float* __restrict__ H) {
    extern __shared__ float s[];
    float* sAh = s;                     // 128 x 36
    float* sAl = s + 128 * LDS_A;
    float* sBh = s + 2 * 128 * LDS_A;   // [n][k] 128 x 36
    float* sBl = s + 3 * 128 * LDS_A;

    const int tid = threadIdx.x;
    const int wid = tid >> 5;
    const int wm = wid >> 2;            // 0..1  (64-row half)
    const int wn = wid & 3;             // 0..3  (32-col strip)
    const int rowBase = blockIdx.x * 128;

    const int srow = tid >> 1;          // staging: 2 threads per row
    const int scol0 = (tid & 1) * 16;

    wmma::fragment<wmma::accumulator, 16, 16, 8, float> acc[4][2];
    #pragma unroll
    for (int mi = 0; mi < 4; mi++)
        #pragma unroll
        for (int ni = 0; ni < 2; ni++) wmma::fill_fragment(acc[mi][ni], 0.f);

    const int nch = F >> 5;
    for (int c = 0; c < nch; c++) {
        // stage A (split on the fly) and B (pre-split)
        #pragma unroll
        for (int q = 0; q < 4; q++) {
            int col = scol0 + q * 4;
            int grow = rowBase + srow;
            float4 v = make_float4(0.f, 0.f, 0.f, 0.f);
            if (grow < N) v = *(const float4*)(X + (size_t)grow * F + c * 32 + col);
            uint32_t h0 = tf32_rna(v.x), h1 = tf32_rna(v.y),
                     h2 = tf32_rna(v.z), h3 = tf32_rna(v.w);
            *(float4*)(sAh + srow * LDS_A + col) =
                make_float4(__uint_as_float(h0), __uint_as_float(h1),
                            __uint_as_float(h2), __uint_as_float(h3));
            float4 lo;
            lo.x = __uint_as_float(tf32_rna(v.x - __uint_as_float(h0)));
            lo.y = __uint_as_float(tf32_rna(v.y - __uint_as_float(h1)));
            lo.z = __uint_as_float(tf32_rna(v.z - __uint_as_float(h2)));
            lo.w = __uint_as_float(tf32_rna(v.w - __uint_as_float(h3)));
            *(float4*)(sAl + srow * LDS_A + col) = lo;

            *(float4*)(sBh + srow * LDS_A + col) =
                *(const float4*)(Bhg + (size_t)srow * F + c * 32 + col);
            *(float4*)(sBl + srow * LDS_A + col) =
                *(const float4*)(Blg + (size_t)srow * F + c * 32 + col);
        }
        __syncthreads();

        #pragma unroll
        for (int kk = 0; kk < 32; kk += 8) {
            wmma::fragment<wmma::matrix_a, 16, 16, 8, wmma::precision::tf32, wmma::row_major> ah[4], al[4];
            wmma::fragment<wmma::matrix_b, 16, 16, 8, wmma::precision::tf32, wmma::col_major> bh[2], bl[2];
            #pragma unroll
            for (int mi = 0; mi < 4; mi++) {
                wmma::load_matrix_sync(ah[mi], sAh + (wm * 64 + mi * 16) * LDS_A + kk, LDS_A);
                wmma::load_matrix_sync(al[mi], sAl + (wm * 64 + mi * 16) * LDS_A + kk, LDS_A);
            }
            #pragma unroll
            for (int ni = 0; ni < 2; ni++) {
                wmma::load_matrix_sync(bh[ni], sBh + (wn * 32 + ni * 16) * LDS_A + kk, LDS_A);
                wmma::load_matrix_sync(bl[ni], sBl + (wn * 32 + ni * 16) * LDS_A + kk, LDS_A);
            }
            #pragma unroll
            for (int mi = 0; mi < 4; mi++)
                #pragma unroll
                for (int ni = 0; ni < 2; ni++) {
                    wmma::mma_sync(acc[mi][ni], ah[mi], bh[ni], acc[mi][ni]);
                    wmma::mma_sync(acc[mi][ni], ah[mi], bl[ni], acc[mi][ni]);
                    wmma::mma_sync(acc[mi][ni], al[mi], bh[ni], acc[mi][ni]);
                }
        }
        __syncthreads();
    }

    if (rowBase + 128 <= N) {
        // full tile: store fragments straight to global
        #pragma unroll
        for (int mi = 0; mi < 4; mi++)
            #pragma unroll
            for (int ni = 0; ni < 2; ni++)
                wmma::store_matrix_sync(
                    H + (size_t)(rowBase + wm * 64 + mi * 16) * 128 + wn * 32 + ni * 16,
                    acc[mi][ni], 128, wmma::mem_row_major);
    } else {
        // ragged tail: stage in smem (stride 132), predicated copy
        float* st = s;  // 128*132 = 16896 floats <= 4*128*36 = 18432
        #pragma unroll
        for (int mi = 0; mi < 4; mi++)
            #pragma unroll
            for (int ni = 0; ni < 2; ni++)
                wmma::store_matrix_sync(
                    st + (size_t)(wm * 64 + mi * 16) * 132 + wn * 32 + ni * 16,
                    acc[mi][ni], 132, wmma::mem_row_major);
        __syncthreads();
        for (int e = tid; e < 128 * 32; e += 256) {
            int r = e >> 5;                 // 128 rows, 8 float4-groups... do scalar x4
            int grow = rowBase + r;
            if (grow < N) {
                int cb = (e & 31) * 4;
                *(float4*)(H + (size_t)grow * 128 + cb) = *(float4*)(st + r * 132 + cb);
            }
        }
    }
}

// warp per node: x' = relu(sum_in h[src]*dis[src]*dis[n] + h[n]/deg + b); also h_s = x' . Ws
__global__ void k_agg(const float* __restrict__ b, const float* __restrict__ Ws, int N) {
    int gid = blockIdx.x * blockDim.x + threadIdx.x;
    int w = gid >> 5, lane = gid & 31;
    if (w >= N) return;
    int beg = g_rowptr[w], end = g_rowptr[w + 1];
    float dn = g_dis[w];
    float4 acc = make_float4(0.f, 0.f, 0.f, 0.f);
    for (int e = beg; e < end; e++) {
        int s = g_csr[e];
        float nm = g_dis[s] * dn;
        float4 hv = *(const float4*)&g_h[s * NH + lane * 4];
        acc.x += hv.x * nm; acc.y += hv.y * nm;
        acc.z += hv.z * nm; acc.w += hv.w * nm;
    }
    float di = g_dinv[w];
    float4 hw = *(const float4*)&g_h[w * NH + lane * 4];
    float4 bb = *(const float4*)&b[lane * 4];
    float4 o;
    o.x = fmaxf(acc.x + hw.x * di + bb.x, 0.f);
    o.y = fmaxf(acc.y + hw.y * di + bb.y, 0.f);
    o.z = fmaxf(acc.z + hw.z * di + bb.z, 0.f);
    o.w = fmaxf(acc.w + hw.w * di + bb.w, 0.f);
    *(float4*)&g_xa[w * NH + lane * 4] = o;
    float4 wv = *(const float4*)&Ws[lane * 4];
    float d = o.x * wv.x + o.y * wv.y + o.z * wv.z + o.w * wv.w;
    #pragma unroll
    for (int off = 16; off; off >>= 1) d += __shfl_xor_sync(0xffffffffu, d, off);
    if (lane == 0) g_hs[w] = d;
}

__global__ void k_sagg(const float* __restrict__ bs, int N) {
    int i = blockIdx.x * blockDim.x + threadIdx.x;
    if (i >= N) return;
    int beg = g_rowptr[i], end = g_rowptr[i + 1];
    float s = 0.f;
    for (int e = beg; e < end; e++) {
        int u = g_csr[e];
        s += g_hs[u] * g_dis[u];
    }
    g_score[i] = s * g_dis[i] + g_hs[i] * g_dinv[i] + bs[0];
}

// block per graph: bitonic sort (score desc, idx asc), then fused pool + readout
__launch_bounds__(1024)
__global__ void k_topk(int n, int k) {
    __shared__ float ss[2048];
    __shared__ int   si[2048];
    int g = blockIdx.x, tid = threadIdx.x;
    for (int j = tid; j < 2048; j += 1024) {
        ss[j] = (j < n) ? g_score[g * n + j] : -3.402823466e38f;
        si[j] = j;
    }
    __syncthreads();
    for (int kk = 2; kk <= 2048; kk <<= 1) {
        for (int jj = kk >> 1; jj > 0; jj >>= 1) {
            for (int i = tid; i < 2048; i += 1024) {
                int l = i ^ jj;
                if (l > i) {
                    float si_ = ss[i], sl_ = ss[l];
                    int ii_ = si[i], il_ = si[l];
                    bool before = (si_ > sl_) || (si_ == sl_ && ii_ < il_);
                    bool asc = ((i & kk) == 0);
                    if (asc != before) {
                        ss[i] = sl_; ss[l] = si_;
                        si[i] = il_; si[l] = ii_;
                    }
                }
            }
            __syncthreads();
        }
    }
    for (int j = tid; j < k; j += 1024) {
        int p = g * n + si[j];
        g_perm[g * k + j] = p;
        g_map[p] = g * k + j;
    }
    __syncthreads();
    // fused pool + readout: 8 node-groups x 128 features
    int f = tid & 127, grp = tid >> 7;
    float mx = -3.402823466e38f, sm = 0.f;
    for (int i = grp; i < k; i += 8) {
        int p = g * n + si[i];
        float ts = tanhf(ss[i]);   // sorted score at position i
        float v = g_xa[p * NH + f] * ts;
        g_xb[(size_t)(g * k + i) * NH + f] = v;
        mx = fmaxf(mx, v); sm += v;
    }
    __syncthreads();
    ss[tid] = mx;
    ss[1024 + tid] = sm;
    __syncthreads();
    if (tid < 128) {
        float m = ss[tid], s2 = ss[1024 + tid];
        #pragma unroll
        for (int g2 = 1; g2 < 8; g2++) {
            m = fmaxf(m, ss[g2 * 128 + tid]);
            s2 += ss[1024 + g2 * 128 + tid];
        }
        g_x123[g * (2 * NH) + tid]      += m;
        g_x123[g * (2 * NH) + NH + tid] += s2 / (float)k;
    }
}

__global__ void k_filter(const int* __restrict__ src, const int* __restrict__ dst,
                         const int* __restrict__ cnt,
                         int* __restrict__ nsrc, int* __restrict__ ndst,
                         int* __restrict__ ncnt) {
    int i = blockIdx.x * blockDim.x + threadIdx.x;
    if (i >= *cnt) return;
    int a = g_map[src[i]], b = g_map[dst[i]];
    if (a >= 0 && b >= 0) {
        int p = atomicAdd(ncnt, 1);
        nsrc[p] = a; ndst[p] = b;
    }
}

__global__ void k_final(const float* __restrict__ Wl, const float* __restrict__ bl,
                        float* __restrict__ out) {
    int g = blockIdx.x, o = threadIdx.x;
    float acc = bl[o];
    #pragma unroll 4
    for (int f = 0; f < 2 * NH; f++)
        acc = fmaf(g_x123[g * (2 * NH) + f], Wl[f * NH + o], acc);
    out[g * NH + o] = fmaxf(acc, 0.f);
}

// ---------------- host driver ----------------
#define GEMM_SMEM (4 * 128 * LDS_A * 4)

static void run_stage(const float* xin, int F, int Nin, int n, int k,
                      const float* Bh, const float* Bl,
                      const float* b, const float* bs,
                      const float* Ws,
                      const int* src, const int* dst, const int* cnt,
                      int* nsrc, int* ndst, int* ncnt, bool filter,
                      float* p_h) {
    const int EB = (E0 + 255) / 256;
    int nb = (Nin + 1023) / 1024;
    k_reset<<<(Nin + 255) / 256, 256>>>(Nin);
    k_count<<<EB, 256>>>(dst, cnt);
    k_scan1<<<nb, 1024>>>(Nin);
    k_gemm_mma<<<(Nin + 127) / 128, 256, GEMM_SMEM>>>(xin, Bh, Bl, Nin, F, p_h);
    k_scan2<<<1, 32>>>(nb);
    k_scan3<<<(Nin + 255) / 256, 256>>>(Nin, cnt);
    k_csr<<<EB, 256>>>(src, dst, cnt);
    k_agg<<<(Nin * 32 + 255) / 256, 256>>>(b, Ws, Nin);
    k_sagg<<<(Nin + 255) / 256, 256>>>(bs, Nin);
    k_topk<<<BNUM, 1024>>>(n, k);
    if (filter) k_filter<<<EB, 256>>>(src, dst, cnt, nsrc, ndst, ncnt);
}

extern "C" void kernel_launch(void* const* d_in, const int* in_sizes, int n_in,
                              void* d_out, int out_size) {
    const float* x   = (const float*)d_in[0];
    const float* W1  = (const float*)d_in[1];
    const float* b1  = (const float*)d_in[2];
    const float* Ws1 = (const float*)d_in[3];
    const float* bs1 = (const float*)d_in[4];
    const float* W2  = (const float*)d_in[5];
    const float* b2  = (const float*)d_in[6];
    const float* Ws2 = (const float*)d_in[7];
    const float* bs2 = (const float*)d_in[8];
    const float* W3  = (const float*)d_in[9];
    const float* b3  = (const float*)d_in[10];
    const float* Ws3 = (const float*)d_in[11];
    const float* bs3 = (const float*)d_in[12];
    const float* Wl  = (const float*)d_in[13];
    const float* bl  = (const float*)d_in[14];
    const int*   ei  = (const int*)d_in[15];
    float* out = (float*)d_out;

    int *p_es0, *p_ed0, *p_es1, *p_ed1, *p_cnt;
    float *p_xb, *p_Wh, *p_Wl, *p_h;
    cudaGetSymbolAddress((void**)&p_es0, g_esrc0);
    cudaGetSymbolAddress((void**)&p_ed0, g_edst0);
    cudaGetSymbolAddress((void**)&p_es1, g_esrc1);
    cudaGetSymbolAddress((void**)&p_ed1, g_edst1);
    cudaGetSymbolAddress((void**)&p_cnt, g_cnt);
    cudaGetSymbolAddress((void**)&p_xb,  g_xb);
    cudaGetSymbolAddress((void**)&p_Wh,  g_Wh);
    cudaGetSymbolAddress((void**)&p_Wl,  g_Wl);
    cudaGetSymbolAddress((void**)&p_h,   g_h);
    cudaFuncSetAttribute(k_gemm_mma, cudaFuncAttributeMaxDynamicSharedMemorySize, GEMM_SMEM);

    k_init<<<(BNUM * 2 * NH + 255) / 256, 256>>>();
    k_splitW<<<256, 256>>>(W1, W2, W3);

    // stage 1: N=100000, F=256, n/graph=2000 -> k=1600   (gemm is launch index 5 for ncu)
    run_stage(x, FIN, 100000, 2000, 1600, p_Wh, p_Wl, b1, bs1, Ws1,
              ei, ei + E0, p_cnt + 0, p_es0, p_ed0, p_cnt + 1, true, p_h);
    // stage 2: N=80000, F=128, n/graph=1600 -> k=1280
    run_stage(p_xb, NH, 80000, 1600, 1280, p_Wh + 32768, p_Wl + 32768, b2, bs2, Ws2,
              p_es0, p_ed0, p_cnt + 1, p_es1, p_ed1, p_cnt + 2, true, p_h);
    // stage 3: N=64000, F=128, n/graph=1280 -> k=1024 (no edge filter needed)
    run_stage(p_xb, NH, 64000, 1280, 1024, p_Wh + 49152, p_Wl + 49152, b3, bs3, Ws3,
              p_es1, p_ed1, p_cnt + 2, nullptr, nullptr, nullptr, false, p_h);

    k_final<<<BNUM, NH>>>(Wl, bl, out);
}

// round 4
// speedup vs baseline: 1.2560x; 1.2560x over previous
#include <cuda_runtime.h>
#include <math.h>
#include <stdint.h>

#define BNUM  50
#define E0    600000
#define FIN   256
#define NH    128
#define N0MAX 100000
#define N1MAX 80000

// ---------------- scratch (device globals; no allocs allowed) ----------------
__device__ float g_h[N0MAX * NH];        // GEMM output h = x @ W
__device__ float g_xa[N0MAX * NH];       // conv output x' (post-relu)
__device__ float g_xb[N1MAX * NH];       // pooled features
__device__ float g_hs[N0MAX];            // score projection h_s = x' @ Ws
__device__ float g_score[N0MAX];
__device__ int   g_deg[N0MAX];
__device__ float g_dis[N0MAX];           // rsqrt(deg+1)
__device__ float g_dinv[N0MAX];          // 1/(deg+1)
__device__ int   g_rowptr[N0MAX + 1];
__device__ int   g_cursor[N0MAX];
__device__ int   g_exsc[N0MAX];
__device__ int   g_bsum[128];
__device__ int   g_csr[E0];              // src ids bucketed by dst
__device__ int   g_esrc0[E0], g_edst0[E0];
__device__ int   g_esrc1[E0], g_edst1[E0];
__device__ int   g_perm[N1MAX];
__device__ int   g_map[N0MAX];
__device__ float g_x123[BNUM * 2 * NH];  // x1+x2+x3 accumulator
__device__ int   g_cnt[4];               // [0]=E stage1, [1]=E after pool1, [2]=after pool2

// ---------------- kernels ----------------
__global__ void k_init() {
    int t = blockIdx.x * blockDim.x + threadIdx.x;
    if (t < BNUM * 2 * NH) g_x123[t] = 0.f;
    if (t == 0) { g_cnt[0] = E0; g_cnt[1] = 0; g_cnt[2] = 0; }
}

__global__ void k_reset(int N) {
    int i = blockIdx.x * blockDim.x + threadIdx.x;
    if (i < N) { g_deg[i] = 0; g_map[i] = -1; }
}

__global__ void k_count(const int* __restrict__ dst, const int* __restrict__ cnt) {
    int i = blockIdx.x * blockDim.x + threadIdx.x;
    if (i < *cnt) atomicAdd(&g_deg[dst[i]], 1);
}

// scan part 1 + fused degnorm
__global__ void k_scan1(int N) {
    __shared__ int sm[1024];
    int i = blockIdx.x * 1024 + threadIdx.x;
    int v = (i < N) ? g_deg[i] : 0;
    if (i < N) {
        float d = (float)v + 1.0f;
        g_dinv[i] = 1.0f / d;
        g_dis[i]  = rsqrtf(d);
    }
    sm[threadIdx.x] = v;
    __syncthreads();
    for (int off = 1; off < 1024; off <<= 1) {
        int t = (threadIdx.x >= off) ? sm[threadIdx.x - off] : 0;
        __syncthreads();
        sm[threadIdx.x] += t;
        __syncthreads();
    }
    if (i < N) g_exsc[i] = sm[threadIdx.x] - v;
    if (threadIdx.x == 1023) g_bsum[blockIdx.x] = sm[1023];
}

__global__ void k_scan2(int nb) {
    if (threadIdx.x == 0) {
        int run = 0;
        for (int i = 0; i < nb; i++) { int t = g_bsum[i]; g_bsum[i] = run; run += t; }
    }
}

__global__ void k_scan3(int N, const int* __restrict__ cnt) {
    int i = blockIdx.x * blockDim.x + threadIdx.x;
    if (i < N) {
        int r = g_exsc[i] + g_bsum[i >> 10];
        g_rowptr[i] = r;
        g_cursor[i] = r;
    }
    if (i == 0) g_rowptr[N] = *cnt;
}

__global__ void k_csr(const int* __restrict__ src, const int* __restrict__ dst,
                      const int* __restrict__ cnt) {
    int i = blockIdx.x * blockDim.x + threadIdx.x;
    if (i < *cnt) {
        int d = dst[i];
        int p = atomicAdd(&g_cursor[d], 1);
        g_csr[p] = src[i];
    }
}

// h = X @ W   (X: [N,F] row-major, W: [F,128] row-major) -> g_h
// BM=128, BN=128, BK=16, 256 threads, 8x8 register tile per thread
__launch_bounds__(256)
__global__ void k_gemm(const float* __restrict__ X, const float* __restrict__ W,
                       int N, int F) {
    __shared__ float As[16 * 128];   // transposed: As[kk][row]
    __shared__ float Bs[16 * 128];   // Bs[kk][col]
    int tid = threadIdx.x;
    int tx = tid & 15, ty = tid >> 4;
    int rowBase = blockIdx.x * 128;
    float acc[8][8];
    #pragma unroll
    for (int r = 0; r < 8; r++)
        #pragma unroll
        for (int c = 0; c < 8; c++) acc[r][c] = 0.f;

    for (int kt = 0; kt < F; kt += 16) {
        #pragma unroll
        for (int q2 = 0; q2 < 2; q2++) {
            int q = tid * 2 + q2;
            int ar = q >> 2, ac4 = q & 3;
            int grow = rowBase + ar;
            float4 v = make_float4(0.f, 0.f, 0.f, 0.f);
            if (grow < N) v = *(const float4*)&X[(size_t)grow * F + kt + ac4 * 4];
            As[(ac4 * 4 + 0) * 128 + ar] = v.x;
            As[(ac4 * 4 + 1) * 128 + ar] = v.y;
            As[(ac4 * 4 + 2) * 128 + ar] = v.z;
            As[(ac4 * 4 + 3) * 128 + ar] = v.w;
        }
        #pragma unroll
        for (int q2 = 0; q2 < 2; q2++) {
            int q = tid * 2 + q2;
            int br = q >> 5, bc4 = q & 31;
            *(float4*)&Bs[br * 128 + bc4 * 4] =
                *(const float4*)&W[(size_t)(kt + br) * 128 + bc4 * 4];
        }
        __syncthreads();
        #pragma unroll
        for (int kk = 0; kk < 16; kk++) {
            float4 a0 = *(float4*)&As[kk * 128 + ty * 8];
            float4 a1 = *(float4*)&As[kk * 128 + ty * 8 + 4];
            float4 b0 = *(float4*)&Bs[kk * 128 + tx * 8];
            float4 b1 = *(float4*)&Bs[kk * 128 + tx * 8 + 4];
            float a[8] = {a0.x, a0.y, a0.z, a0.w, a1.x, a1.y, a1.z, a1.w};
            float b[8] = {b0.x, b0.y, b0.z, b0.w, b1.x, b1.y, b1.z, b1.w};
            #pragma unroll
            for (int r = 0; r < 8; r++)
                #pragma unroll
                for (int c = 0; c < 8; c++) acc[r][c] += a[r] * b[c];
        }
        __syncthreads();
    }
    #pragma unroll
    for (int r = 0; r < 8; r++) {
        int grow = rowBase + ty * 8 + r;
        if (grow < N) {
            *(float4*)&g_h[(size_t)grow * NH + tx * 8] =
                make_float4(acc[r][0], acc[r][1], acc[r][2], acc[r][3]);
            *(float4*)&g_h[(size_t)grow * NH + tx * 8 + 4] =
                make_float4(acc[r][4], acc[r][5], acc[r][6], acc[r][7]);
        }
    }
}

// warp per node: x' = relu(sum_in h[src]*dis[src]*dis[n] + h[n]/deg + b); also h_s = x' . Ws
__global__ void k_agg(const float* __restrict__ b, const float* __restrict__ Ws, int N) {
    int gid = blockIdx.x * blockDim.x + threadIdx.x;
    int w = gid >> 5, lane = gid & 31;
    if (w >= N) return;
    int beg = g_rowptr[w], end = g_rowptr[w + 1];
    float dn = g_dis[w];
    float4 acc = make_float4(0.f, 0.f, 0.f, 0.f);
    for (int e = beg; e < end; e++) {
        int s = g_csr[e];
        float nm = g_dis[s] * dn;
        float4 hv = *(const float4*)&g_h[s * NH + lane * 4];
        acc.x += hv.x * nm; acc.y += hv.y * nm;
        acc.z += hv.z * nm; acc.w += hv.w * nm;
    }
    float di = g_dinv[w];
    float4 hw = *(const float4*)&g_h[w * NH + lane * 4];
    float4 bb = *(const float4*)&b[lane * 4];
    float4 o;
    o.x = fmaxf(acc.x + hw.x * di + bb.x, 0.f);
    o.y = fmaxf(acc.y + hw.y * di + bb.y, 0.f);
    o.z = fmaxf(acc.z + hw.z * di + bb.z, 0.f);
    o.w = fmaxf(acc.w + hw.w * di + bb.w, 0.f);
    *(float4*)&g_xa[w * NH + lane * 4] = o;
    float4 wv = *(const float4*)&Ws[lane * 4];
    float d = o.x * wv.x + o.y * wv.y + o.z * wv.z + o.w * wv.w;
    #pragma unroll
    for (int off = 16; off; off >>= 1) d += __shfl_xor_sync(0xffffffffu, d, off);
    if (lane == 0) g_hs[w] = d;
}

__global__ void k_sagg(const float* __restrict__ bs, int N) {
    int i = blockIdx.x * blockDim.x + threadIdx.x;
    if (i >= N) return;
    int beg = g_rowptr[i], end = g_rowptr[i + 1];
    float s = 0.f;
    for (int e = beg; e < end; e++) {
        int u = g_csr[e];
        s += g_hs[u] * g_dis[u];
    }
    g_score[i] = s * g_dis[i] + g_hs[i] * g_dinv[i] + bs[0];
}

// block per graph: bitonic sort (score desc, idx asc), then fused pool + readout
__launch_bounds__(1024)
__global__ void k_topk(int n, int k) {
    __shared__ float ss[2048];
    __shared__ int   si[2048];
    int g = blockIdx.x, tid = threadIdx.x;
    for (int j = tid; j < 2048; j += 1024) {
        ss[j] = (j < n) ? g_score[g * n + j] : -3.402823466e38f;
        si[j] = j;
    }
    __syncthreads();
    for (int kk = 2; kk <= 2048; kk <<= 1) {
        for (int jj = kk >> 1; jj > 0; jj >>= 1) {
            for (int i = tid; i < 2048; i += 1024) {
                int l = i ^ jj;
                if (l > i) {
                    float si_ = ss[i], sl_ = ss[l];
                    int ii_ = si[i], il_ = si[l];
                    bool before = (si_ > sl_) || (si_ == sl_ && ii_ < il_);
                    bool asc = ((i & kk) == 0);
                    if (asc != before) {
                        ss[i] = sl_; ss[l] = si_;
                        si[i] = il_; si[l] = ii_;
                    }
                }
            }
            __syncthreads();
        }
    }
    for (int j = tid; j < k; j += 1024) {
        int p = g * n + si[j];
        g_perm[g * k + j] = p;
        g_map[p] = g * k + j;
    }
    __syncthreads();
    // fused pool + readout: 8 node-groups x 128 features
    int f = tid & 127, grp = tid >> 7;
    float mx = -3.402823466e38f, sm = 0.f;
    for (int i = grp; i < k; i += 8) {
        int p = g * n + si[i];
        float ts = tanhf(ss[i]);   // sorted score at position i
        float v = g_xa[p * NH + f] * ts;
        g_xb[(size_t)(g * k + i) * NH + f] = v;
        mx = fmaxf(mx, v); sm += v;
    }
    __syncthreads();
    ss[tid] = mx;
    ss[1024 + tid] = sm;
    __syncthreads();
    if (tid < 128) {
        float m = ss[tid], s2 = ss[1024 + tid];
        #pragma unroll
        for (int g2 = 1; g2 < 8; g2++) {
            m = fmaxf(m, ss[g2 * 128 + tid]);
            s2 += ss[1024 + g2 * 128 + tid];
        }
        g_x123[g * (2 * NH) + tid]      += m;
        g_x123[g * (2 * NH) + NH + tid] += s2 / (float)k;
    }
}

__global__ void k_filter(const int* __restrict__ src, const int* __restrict__ dst,
                         const int* __restrict__ cnt,
                         int* __restrict__ nsrc, int* __restrict__ ndst,
                         int* __restrict__ ncnt) {
    int i = blockIdx.x * blockDim.x + threadIdx.x;
    if (i >= *cnt) return;
    int a = g_map[src[i]], b = g_map[dst[i]];
    if (a >= 0 && b >= 0) {
        int p = atomicAdd(ncnt, 1);
        nsrc[p] = a; ndst[p] = b;
    }
}

__global__ void k_final(const float* __restrict__ Wl, const float* __restrict__ bl,
                        float* __restrict__ out) {
    int g = blockIdx.x, o = threadIdx.x;
    float acc = bl[o];
    #pragma unroll 4
    for (int f = 0; f < 2 * NH; f++)
        acc = fmaf(g_x123[g * (2 * NH) + f], Wl[f * NH + o], acc);
    out[g * NH + o] = fmaxf(acc, 0.f);
}

// ---------------- host driver ----------------
static void run_stage(const float* xin, int F, int Nin, int n, int k,
                      const float* W, const float* b, const float* Ws, const float* bs,
                      const int* src, const int* dst, const int* cnt,
                      int* nsrc, int* ndst, int* ncnt, bool filter) {
    const int EB = (E0 + 255) / 256;
    int nb = (Nin + 1023) / 1024;
    k_reset<<<(Nin + 255) / 256, 256>>>(Nin);
    k_count<<<EB, 256>>>(dst, cnt);
    // GEMM right after count -> stage-1 GEMM is overall launch index 3 (ncu window)
    k_gemm<<<(Nin + 127) / 128, 256>>>(xin, W, Nin, F);
    k_scan1<<<nb, 1024>>>(Nin);
    k_scan2<<<1, 32>>>(nb);
    k_scan3<<<(Nin + 255) / 256, 256>>>(Nin, cnt);
    k_csr<<<EB, 256>>>(src, dst, cnt);
    k_agg<<<(Nin * 32 + 255) / 256, 256>>>(b, Ws, Nin);
    k_sagg<<<(Nin + 255) / 256, 256>>>(bs, Nin);
    k_topk<<<BNUM, 1024>>>(n, k);
    if (filter) k_filter<<<EB, 256>>>(src, dst, cnt, nsrc, ndst, ncnt);
}

extern "C" void kernel_launch(void* const* d_in, const int* in_sizes, int n_in,
                              void* d_out, int out_size) {
    const float* x   = (const float*)d_in[0];
    const float* W1  = (const float*)d_in[1];
    const float* b1  = (const float*)d_in[2];
    const float* Ws1 = (const float*)d_in[3];
    const float* bs1 = (const float*)d_in[4];
    const float* W2  = (const float*)d_in[5];
    const float* b2  = (const float*)d_in[6];
    const float* Ws2 = (const float*)d_in[7];
    const float* bs2 = (const float*)d_in[8];
    const float* W3  = (const float*)d_in[9];
    const float* b3  = (const float*)d_in[10];
    const float* Ws3 = (const float*)d_in[11];
    const float* bs3 = (const float*)d_in[12];
    const float* Wl  = (const float*)d_in[13];
    const float* bl  = (const float*)d_in[14];
    const int*   ei  = (const int*)d_in[15];
    float* out = (float*)d_out;

    int *p_es0, *p_ed0, *p_es1, *p_ed1, *p_cnt;
    float* p_xb;
    cudaGetSymbolAddress((void**)&p_es0, g_esrc0);
    cudaGetSymbolAddress((void**)&p_ed0, g_edst0);
    cudaGetSymbolAddress((void**)&p_es1, g_esrc1);
    cudaGetSymbolAddress((void**)&p_ed1, g_edst1);
    cudaGetSymbolAddress((void**)&p_cnt, g_cnt);
    cudaGetSymbolAddress((void**)&p_xb,  g_xb);

    k_init<<<(BNUM * 2 * NH + 255) / 256, 256>>>();

    // stage 1: N=100000, F=256, n/graph=2000 -> k=1600
    run_stage(x, FIN, 100000, 2000, 1600, W1, b1, Ws1, bs1,
              ei, ei + E0, p_cnt + 0, p_es0, p_ed0, p_cnt + 1, true);
    // stage 2: N=80000, F=128, n/graph=1600 -> k=1280
    run_stage(p_xb, NH, 80000, 1600, 1280, W2, b2, Ws2, bs2,
              p_es0, p_ed0, p_cnt + 1, p_es1, p_ed1, p_cnt + 2, true);
    // stage 3: N=64000, F=128, n/graph=1280 -> k=1024 (no edge filter needed)
    run_stage(p_xb, NH, 64000, 1280, 1024, W3, b3, Ws3, bs3,
              p_es1, p_ed1, p_cnt + 2, nullptr, nullptr, nullptr, false);

    k_final<<<BNUM, NH>>>(Wl, bl, out);
}

// round 5
// speedup vs baseline: 1.3654x; 1.0871x over previous
#include <cuda_runtime.h>
#include <math.h>
#include <stdint.h>

#define BNUM  50
#define E0    600000
#define FIN   256
#define NH    128
#define N0MAX 100000
#define N1MAX 80000

// ---------------- scratch (device globals; no allocs allowed) ----------------
__device__ float g_h[N0MAX * NH];        // GEMM output h = x @ W
__device__ float g_xa[N0MAX * NH];       // conv output x' (post-relu)
__device__ float g_xb[N1MAX * NH];       // pooled features
__device__ float g_hs[N0MAX];            // score projection h_s = x' @ Ws
__device__ float g_score[N0MAX];
__device__ int   g_deg[N0MAX];
__device__ float g_dis[N0MAX];           // rsqrt(deg+1)
__device__ float g_dinv[N0MAX];          // 1/(deg+1)
__device__ int   g_rowptr[N0MAX + 1];
__device__ int   g_cursor[N0MAX];
__device__ int   g_exsc[N0MAX];
__device__ int   g_bsum[128];
__device__ int   g_csr[E0];              // src ids bucketed by dst
__device__ int   g_esrc0[E0], g_edst0[E0];
__device__ int   g_esrc1[E0], g_edst1[E0];
__device__ int   g_perm[N1MAX];
__device__ int   g_map[N0MAX];
__device__ float g_x123[BNUM * 2 * NH];  // x1+x2+x3 accumulator
__device__ int   g_cnt[4];               // [0]=E stage1, [1]=E after pool1, [2]=after pool2

// ---------------- kernels ----------------
__global__ void k_init() {
    int t = blockIdx.x * blockDim.x + threadIdx.x;
    if (t < BNUM * 2 * NH) g_x123[t] = 0.f;
    if (t == 0) { g_cnt[0] = E0; g_cnt[1] = 0; g_cnt[2] = 0; }
}

__global__ void k_reset(int N) {
    int i = blockIdx.x * blockDim.x + threadIdx.x;
    if (i < N) { g_deg[i] = 0; g_map[i] = -1; }
}

__global__ void k_count(const int* __restrict__ dst, const int* __restrict__ cnt) {
    int i = blockIdx.x * blockDim.x + threadIdx.x;
    if (i < *cnt) atomicAdd(&g_deg[dst[i]], 1);
}

// scan part 1 + fused degnorm
__global__ void k_scan1(int N) {
    __shared__ int sm[1024];
    int i = blockIdx.x * 1024 + threadIdx.x;
    int v = (i < N) ? g_deg[i] : 0;
    if (i < N) {
        float d = (float)v + 1.0f;
        g_dinv[i] = 1.0f / d;
        g_dis[i]  = rsqrtf(d);
    }
    sm[threadIdx.x] = v;
    __syncthreads();
    for (int off = 1; off < 1024; off <<= 1) {
        int t = (threadIdx.x >= off) ? sm[threadIdx.x - off] : 0;
        __syncthreads();
        sm[threadIdx.x] += t;
        __syncthreads();
    }
    if (i < N) g_exsc[i] = sm[threadIdx.x] - v;
    if (threadIdx.x == 1023) g_bsum[blockIdx.x] = sm[1023];
}

__global__ void k_scan2(int nb) {
    if (threadIdx.x == 0) {
        int run = 0;
        for (int i = 0; i < nb; i++) { int t = g_bsum[i]; g_bsum[i] = run; run += t; }
    }
}

__global__ void k_scan3(int N, const int* __restrict__ cnt) {
    int i = blockIdx.x * blockDim.x + threadIdx.x;
    if (i < N) {
        int r = g_exsc[i] + g_bsum[i >> 10];
        g_rowptr[i] = r;
        g_cursor[i] = r;
    }
    if (i == 0) g_rowptr[N] = *cnt;
}

__global__ void k_csr(const int* __restrict__ src, const int* __restrict__ dst,
                      const int* __restrict__ cnt) {
    int i = blockIdx.x * blockDim.x + threadIdx.x;
    if (i < *cnt) {
        int d = dst[i];
        int p = atomicAdd(&g_cursor[d], 1);
        g_csr[p] = src[i];
    }
}

// h = X @ W   (X: [N,F] row-major, W: [F,128] row-major) -> g_h
// BM=128, BN=128, BK=16, 256 threads, 8x8 register tile, double-buffered smem
__launch_bounds__(256)
__global__ void k_gemm(const float* __restrict__ X, const float* __restrict__ W,
                       int N, int F) {
    __shared__ float As[2][16 * 128];   // transposed: As[b][kk][row]
    __shared__ float Bs[2][16 * 128];   // Bs[b][kk][col]
    const int tid = threadIdx.x;
    const int tx = tid & 15, ty = tid >> 4;
    const int rowBase = blockIdx.x * 128;

    // loader geometry: each thread handles 2 adjacent float4 of A and B
    const int ar  = tid >> 1;            // A row 0..127
    const int ac0 = (tid & 1) * 2;       // A col-group: kk range ac0*4 .. ac0*4+7
    const int br0 = tid >> 4;            // B row (kk) 0..15
    const int bc0 = (2 * tid) & 31;      // B col-group

    float acc[8][8];
    #pragma unroll
    for (int r = 0; r < 8; r++)
        #pragma unroll
        for (int c = 0; c < 8; c++) acc[r][c] = 0.f;

    float4 va0, va1, vb0, vb1;

#define LDT(kt) do {                                                            \
    int grow = rowBase + ar;                                                    \
    if (grow < N) {                                                             \
        va0 = *(const float4*)&X[(size_t)grow * F + (kt) + ac0 * 4];            \
        va1 = *(const float4*)&X[(size_t)grow * F + (kt) + ac0 * 4 + 4];        \
    } else {                                                                    \
        va0 = make_float4(0.f, 0.f, 0.f, 0.f);                                  \
        va1 = make_float4(0.f, 0.f, 0.f, 0.f);                                  \
    }                                                                           \
    vb0 = *(const float4*)&W[(size_t)((kt) + br0) * 128 + bc0 * 4];             \
    vb1 = *(const float4*)&W[(size_t)((kt) + br0) * 128 + bc0 * 4 + 4];         \
} while (0)

#define STT(b) do {                                                             \
    As[b][(ac0 * 4 + 0) * 128 + ar] = va0.x;                                    \
    As[b][(ac0 * 4 + 1) * 128 + ar] = va0.y;                                    \
    As[b][(ac0 * 4 + 2) * 128 + ar] = va0.z;                                    \
    As[b][(ac0 * 4 + 3) * 128 + ar] = va0.w;                                    \
    As[b][(ac0 * 4 + 4) * 128 + ar] = va1.x;                                    \
    As[b][(ac0 * 4 + 5) * 128 + ar] = va1.y;                                    \
    As[b][(ac0 * 4 + 6) * 128 + ar] = va1.z;                                    \
    As[b][(ac0 * 4 + 7) * 128 + ar] = va1.w;                                    \
    *(float4*)&Bs[b][br0 * 128 + bc0 * 4]     = vb0;                            \
    *(float4*)&Bs[b][br0 * 128 + bc0 * 4 + 4] = vb1;                            \
} while (0)

    const int T = F >> 4;
    LDT(0);
    STT(0);
    __syncthreads();

    for (int t = 0; t < T; t++) {
        const int cur = t & 1;
        if (t + 1 < T) LDT((t + 1) * 16);
        #pragma unroll
        for (int kk = 0; kk < 16; kk++) {
            float4 a0 = *(float4*)&As[cur][kk * 128 + ty * 8];
            float4 a1 = *(float4*)&As[cur][kk * 128 + ty * 8 + 4];
            float4 b0 = *(float4*)&Bs[cur][kk * 128 + tx * 8];
            float4 b1 = *(float4*)&Bs[cur][kk * 128 + tx * 8 + 4];
            float a[8] = {a0.x, a0.y, a0.z, a0.w, a1.x, a1.y, a1.z, a1.w};
            float b[8] = {b0.x, b0.y, b0.z, b0.w, b1.x, b1.y, b1.z, b1.w};
            #pragma unroll
            for (int r = 0; r < 8; r++)
                #pragma unroll
                for (int c = 0; c < 8; c++) acc[r][c] += a[r] * b[c];
        }
        if (t + 1 < T) STT((t + 1) & 1);
        __syncthreads();
    }
#undef LDT
#undef STT

    #pragma unroll
    for (int r = 0; r < 8; r++) {
        int grow = rowBase + ty * 8 + r;
        if (grow < N) {
            *(float4*)&g_h[(size_t)grow * NH + tx * 8] =
                make_float4(acc[r][0], acc[r][1], acc[r][2], acc[r][3]);
            *(float4*)&g_h[(size_t)grow * NH + tx * 8 + 4] =
                make_float4(acc[r][4], acc[r][5], acc[r][6], acc[r][7]);
        }
    }
}

// warp per node: x' = relu(sum_in h[src]*dis[src]*dis[n] + h[n]/deg + b); also h_s = x' . Ws
__global__ void k_agg(const float* __restrict__ b, const float* __restrict__ Ws, int N) {
    int gid = blockIdx.x * blockDim.x + threadIdx.x;
    int w = gid >> 5, lane = gid & 31;
    if (w >= N) return;
    int beg = g_rowptr[w], end = g_rowptr[w + 1];
    float dn = g_dis[w];
    float4 acc = make_float4(0.f, 0.f, 0.f, 0.f);
    for (int e = beg; e < end; e++) {
        int s = g_csr[e];
        float nm = g_dis[s] * dn;
        float4 hv = *(const float4*)&g_h[s * NH + lane * 4];
        acc.x += hv.x * nm; acc.y += hv.y * nm;
        acc.z += hv.z * nm; acc.w += hv.w * nm;
    }
    float di = g_dinv[w];
    float4 hw = *(const float4*)&g_h[w * NH + lane * 4];
    float4 bb = *(const float4*)&b[lane * 4];
    float4 o;
    o.x = fmaxf(acc.x + hw.x * di + bb.x, 0.f);
    o.y = fmaxf(acc.y + hw.y * di + bb.y, 0.f);
    o.z = fmaxf(acc.z + hw.z * di + bb.z, 0.f);
    o.w = fmaxf(acc.w + hw.w * di + bb.w, 0.f);
    *(float4*)&g_xa[w * NH + lane * 4] = o;
    float4 wv = *(const float4*)&Ws[lane * 4];
    float d = o.x * wv.x + o.y * wv.y + o.z * wv.z + o.w * wv.w;
    #pragma unroll
    for (int off = 16; off; off >>= 1) d += __shfl_xor_sync(0xffffffffu, d, off);
    if (lane == 0) g_hs[w] = d;
}

__global__ void k_sagg(const float* __restrict__ bs, int N) {
    int i = blockIdx.x * blockDim.x + threadIdx.x;
    if (i >= N) return;
    int beg = g_rowptr[i], end = g_rowptr[i + 1];
    float s = 0.f;
    for (int e = beg; e < end; e++) {
        int u = g_csr[e];
        s += g_hs[u] * g_dis[u];
    }
    g_score[i] = s * g_dis[i] + g_hs[i] * g_dinv[i] + bs[0];
}

// block per graph: bitonic sort (score desc, idx asc), then fused pool + readout
__launch_bounds__(1024)
__global__ void k_topk(int n, int k) {
    __shared__ float ss[2048];
    __shared__ int   si[2048];
    int g = blockIdx.x, tid = threadIdx.x;
    for (int j = tid; j < 2048; j += 1024) {
        ss[j] = (j < n) ? g_score[g * n + j] : -3.402823466e38f;
        si[j] = j;
    }
    __syncthreads();
    for (int kk = 2; kk <= 2048; kk <<= 1) {
        for (int jj = kk >> 1; jj > 0; jj >>= 1) {
            for (int i = tid; i < 2048; i += 1024) {
                int l = i ^ jj;
                if (l > i) {
                    float si_ = ss[i], sl_ = ss[l];
                    int ii_ = si[i], il_ = si[l];
                    bool before = (si_ > sl_) || (si_ == sl_ && ii_ < il_);
                    bool asc = ((i & kk) == 0);
                    if (asc != before) {
                        ss[i] = sl_; ss[l] = si_;
                        si[i] = il_; si[l] = ii_;
                    }
                }
            }
            __syncthreads();
        }
    }
    for (int j = tid; j < k; j += 1024) {
        int p = g * n + si[j];
        g_perm[g * k + j] = p;
        g_map[p] = g * k + j;
    }
    __syncthreads();
    // fused pool + readout: 8 node-groups x 128 features
    int f = tid & 127, grp = tid >> 7;
    float mx = -3.402823466e38f, sm = 0.f;
    for (int i = grp; i < k; i += 8) {
        int p = g * n + si[i];
        float ts = tanhf(ss[i]);   // sorted score at position i
        float v = g_xa[p * NH + f] * ts;
        g_xb[(size_t)(g * k + i) * NH + f] = v;
        mx = fmaxf(mx, v); sm += v;
    }
    __syncthreads();
    ss[tid] = mx;
    ss[1024 + tid] = sm;
    __syncthreads();
    if (tid < 128) {
        float m = ss[tid], s2 = ss[1024 + tid];
        #pragma unroll
        for (int g2 = 1; g2 < 8; g2++) {
            m = fmaxf(m, ss[g2 * 128 + tid]);
            s2 += ss[1024 + g2 * 128 + tid];
        }
        g_x123[g * (2 * NH) + tid]      += m;
        g_x123[g * (2 * NH) + NH + tid] += s2 / (float)k;
    }
}

__global__ void k_filter(const int* __restrict__ src, const int* __restrict__ dst,
                         const int* __restrict__ cnt,
                         int* __restrict__ nsrc, int* __restrict__ ndst,
                         int* __restrict__ ncnt) {
    int i = blockIdx.x * blockDim.x + threadIdx.x;
    if (i >= *cnt) return;
    int a = g_map[src[i]], b = g_map[dst[i]];
    if (a >= 0 && b >= 0) {
        int p = atomicAdd(ncnt, 1);
        nsrc[p] = a; ndst[p] = b;
    }
}

__global__ void k_final(const float* __restrict__ Wl, const float* __restrict__ bl,
                        float* __restrict__ out) {
    int g = blockIdx.x, o = threadIdx.x;
    float acc = bl[o];
    #pragma unroll 4
    for (int f = 0; f < 2 * NH; f++)
        acc = fmaf(g_x123[g * (2 * NH) + f], Wl[f * NH + o], acc);
    out[g * NH + o] = fmaxf(acc, 0.f);
}

// ---------------- host driver ----------------
extern "C" void kernel_launch(void* const* d_in, const int* in_sizes, int n_in,
                              void* d_out, int out_size) {
    // one-time side-stream + fork/join events (no device-memory allocation)
    static cudaStream_t s2 = nullptr;
    static cudaEvent_t evF = nullptr, evJ = nullptr;
    if (!s2) {
        cudaStreamCreateWithFlags(&s2, cudaStreamNonBlocking);
        cudaEventCreateWithFlags(&evF, cudaEventDisableTiming);
        cudaEventCreateWithFlags(&evJ, cudaEventDisableTiming);
    }

    const float* x   = (const float*)d_in[0];
    const float* W1  = (const float*)d_in[1];
    const float* b1  = (const float*)d_in[2];
    const float* Ws1 = (const float*)d_in[3];
    const float* bs1 = (const float*)d_in[4];
    const float* W2  = (const float*)d_in[5];
    const float* b2  = (const float*)d_in[6];
    const float* Ws2 = (const float*)d_in[7];
    const float* bs2 = (const float*)d_in[8];
    const float* W3  = (const float*)d_in[9];
    const float* b3  = (const float*)d_in[10];
    const float* Ws3 = (const float*)d_in[11];
    const float* bs3 = (const float*)d_in[12];
    const float* Wl  = (const float*)d_in[13];
    const float* bl  = (const float*)d_in[14];
    const int*   ei  = (const int*)d_in[15];
    float* out = (float*)d_out;

    int *p_es0, *p_ed0, *p_es1, *p_ed1, *p_cnt;
    float* p_xb;
    cudaGetSymbolAddress((void**)&p_es0, g_esrc0);
    cudaGetSymbolAddress((void**)&p_ed0, g_edst0);
    cudaGetSymbolAddress((void**)&p_es1, g_esrc1);
    cudaGetSymbolAddress((void**)&p_ed1, g_edst1);
    cudaGetSymbolAddress((void**)&p_cnt, g_cnt);
    cudaGetSymbolAddress((void**)&p_xb,  g_xb);

    const int EB = (E0 + 255) / 256;

    k_init<<<(BNUM * 2 * NH + 255) / 256, 256>>>();

    // ================= stage 1: N=100000, F=256, n=2000, k=1600 =================
    {
        const int Nin = 100000, n = 2000, kk = 1600;
        int nb = (Nin + 1023) / 1024;
        cudaEventRecord(evF, 0);
        cudaStreamWaitEvent(s2, evF, 0);
        k_reset<<<(Nin + 255) / 256, 256>>>(Nin);
        k_count<<<EB, 256>>>(ei + E0, p_cnt + 0);
        k_gemm<<<(Nin + 127) / 128, 256, 0, s2>>>(x, W1, Nin, FIN);  // launch idx 3
        cudaEventRecord(evJ, s2);
        k_scan1<<<nb, 1024>>>(Nin);
        k_scan2<<<1, 32>>>(nb);
        k_scan3<<<(Nin + 255) / 256, 256>>>(Nin, p_cnt + 0);
        k_csr<<<EB, 256>>>(ei, ei + E0, p_cnt + 0);
        cudaStreamWaitEvent(0, evJ, 0);
        k_agg<<<(Nin * 32 + 255) / 256, 256>>>(b1, Ws1, Nin);
        k_sagg<<<(Nin + 255) / 256, 256>>>(bs1, Nin);
        k_topk<<<BNUM, 1024>>>(n, kk);
    }

    // ================= stage 2: N=80000, F=128, n=1600, k=1280 =================
    {
        const int Nin = 80000, n = 1600, kk = 1280;
        int nb = (Nin + 1023) / 1024;
        cudaEventRecord(evF, 0);                    // after topk1: g_xb ready, g_h free
        cudaStreamWaitEvent(s2, evF, 0);
        k_gemm<<<(Nin + 127) / 128, 256, 0, s2>>>(p_xb, W2, Nin, NH);
        cudaEventRecord(evJ, s2);
        k_filter<<<EB, 256>>>(ei, ei + E0, p_cnt + 0, p_es0, p_ed0, p_cnt + 1);
        k_reset<<<(Nin + 255) / 256, 256>>>(Nin);
        k_count<<<EB, 256>>>(p_ed0, p_cnt + 1);
        k_scan1<<<nb, 1024>>>(Nin);
        k_scan2<<<1, 32>>>(nb);
        k_scan3<<<(Nin + 255) / 256, 256>>>(Nin, p_cnt + 1);
        k_csr<<<EB, 256>>>(p_es0, p_ed0, p_cnt + 1);
        cudaStreamWaitEvent(0, evJ, 0);
        k_agg<<<(Nin * 32 + 255) / 256, 256>>>(b2, Ws2, Nin);
        k_sagg<<<(Nin + 255) / 256, 256>>>(bs2, Nin);
        k_topk<<<BNUM, 1024>>>(n, kk);
    }

    // ================= stage 3: N=64000, F=128, n=1280, k=1024 =================
    {
        const int Nin = 64000, n = 1280, kk = 1024;
        int nb = (Nin + 1023) / 1024;
        cudaEventRecord(evF, 0);
        cudaStreamWaitEvent(s2, evF, 0);
        k_gemm<<<(Nin + 127) / 128, 256, 0, s2>>>(p_xb, W3, Nin, NH);
        cudaEventRecord(evJ, s2);
        k_filter<<<EB, 256>>>(p_es0, p_ed0, p_cnt + 1, p_es1, p_ed1, p_cnt + 2);
        k_reset<<<(Nin + 255) / 256, 256>>>(Nin);
        k_count<<<EB, 256>>>(p_ed1, p_cnt + 2);
        k_scan1<<<nb, 1024>>>(Nin);
        k_scan2<<<1, 32>>>(nb);
        k_scan3<<<(Nin + 255) / 256, 256>>>(Nin, p_cnt + 2);
        k_csr<<<EB, 256>>>(p_es1, p_ed1, p_cnt + 2);
        cudaStreamWaitEvent(0, evJ, 0);
        k_agg<<<(Nin * 32 + 255) / 256, 256>>>(b3, Ws3, Nin);
        k_sagg<<<(Nin + 255) / 256, 256>>>(bs3, Nin);
        k_topk<<<BNUM, 1024>>>(n, kk);
    }

    k_final<<<BNUM, NH>>>(Wl, bl, out);
}